// round 4
// baseline (speedup 1.0000x reference)
#include <cuda_runtime.h>
#include <cstdint>

// Stage 1 (fast, fp32 packed-fma): s[n,k] = c2[k] - 2*dot(emb_n, cent_k),
//   per-row top-4 candidate indices -> g_cand.
// Stage 2 (exact): fp64 dot/x2/c2 for the 4 candidates, then replicate the
//   reference's fp32 rounding chain fl(sqrt(max(fl(fl(x2+c2)-fl(2*xc)),0)))
//   and jax top_k tie-break (lower index). out[row] = centroids[second-max].

#define ROWS 128
#define DK   16
#define KTOT 256
#define DIM  256
#define NMAX 262144

__device__ float  g_c2[KTOT];
__device__ double g_c2d[KTOT];
__device__ int    g_cand[NMAX * 4];

__global__ void c2_kernel(const float* __restrict__ cent) {
    int k = threadIdx.x;
    double s = 0.0;
#pragma unroll 8
    for (int d = 0; d < DIM; ++d) {
        double c = (double)cent[k * DIM + d];
        s += c * c;
    }
    g_c2d[k] = s;
    g_c2[k]  = (float)s;
}

union SMem {
    struct {
        float  emb[DK][ROWS];     // transposed emb tile: [d][row]
        float2 cent[DK][128];     // centroid tile, duplicated {c,c}
    } t;                          // 24KB
    struct {
        float v[ROWS][32];        // per-row candidates (16 threads x top2)
        int   idx[ROWS][32];
    } r;                          // 32KB
};

__device__ __forceinline__ void upd2(float& V1, int& I1, float& V2, int& I2,
                                     float v, int k) {
    bool b1 = (v > V1) || (v == V1 && k < I1);
    bool b2 = (v > V2) || (v == V2 && k < I2);
    if (b1) { V2 = V1; I2 = I1; V1 = v; I1 = k; }
    else if (b2) { V2 = v; I2 = k; }
}

__global__ __launch_bounds__(256)
void neg_sampler_fast(const float* __restrict__ emb,
                      const float* __restrict__ cent, int N) {
    __shared__ SMem sm;
    const int tid = threadIdx.x;
    const int n0  = blockIdx.x * ROWS;
    const int tx  = tid & 15;   // centroid group: k = kp*128 + tx + 16*j
    const int rg  = tid >> 4;   // row group: rows rg*8 .. rg*8+7

    float v1[8], v2[8];
    int   i1[8], i2[8];
#pragma unroll
    for (int p = 0; p < 8; ++p) {
        v1[p] = -__int_as_float(0x7f800000);
        v2[p] = -__int_as_float(0x7f800000);
        i1[p] = 0; i2[p] = 0;
    }

    const int seg = tid & 3;
    const int rr  = tid >> 2;

    for (int kp = 0; kp < 2; ++kp) {
        unsigned long long acc[4][8];
#pragma unroll
        for (int p = 0; p < 4; ++p)
#pragma unroll
            for (int j = 0; j < 8; ++j) acc[p][j] = 0ull;

        for (int dt = 0; dt < DIM; dt += DK) {
            __syncthreads();
#pragma unroll
            for (int it = 0; it < 2; ++it) {
                int row = it * 64 + rr;
                int gr  = n0 + row;
                float4 v = make_float4(0.f, 0.f, 0.f, 0.f);
                if (gr < N)
                    v = *reinterpret_cast<const float4*>(&emb[(size_t)gr * DIM + dt + seg * 4]);
                sm.t.emb[seg * 4 + 0][row] = v.x;
                sm.t.emb[seg * 4 + 1][row] = v.y;
                sm.t.emb[seg * 4 + 2][row] = v.z;
                sm.t.emb[seg * 4 + 3][row] = v.w;
            }
#pragma unroll
            for (int it = 0; it < 2; ++it) {
                int idx = it * 64 + rr;
                int k   = kp * 128 + idx;
                float4 v = *reinterpret_cast<const float4*>(&cent[(size_t)k * DIM + dt + seg * 4]);
                sm.t.cent[seg * 4 + 0][idx] = make_float2(v.x, v.x);
                sm.t.cent[seg * 4 + 1][idx] = make_float2(v.y, v.y);
                sm.t.cent[seg * 4 + 2][idx] = make_float2(v.z, v.z);
                sm.t.cent[seg * 4 + 3][idx] = make_float2(v.w, v.w);
            }
            __syncthreads();

#pragma unroll
            for (int d = 0; d < DK; ++d) {
                unsigned long long a[4], c[8];
#pragma unroll
                for (int p = 0; p < 4; ++p)
                    a[p] = *reinterpret_cast<const unsigned long long*>(
                        &sm.t.emb[d][rg * 8 + 2 * p]);
#pragma unroll
                for (int j = 0; j < 8; ++j)
                    c[j] = *reinterpret_cast<const unsigned long long*>(
                        &sm.t.cent[d][tx + 16 * j]);
#pragma unroll
                for (int p = 0; p < 4; ++p)
#pragma unroll
                    for (int j = 0; j < 8; ++j)
                        asm("fma.rn.f32x2 %0, %1, %2, %0;"
                            : "+l"(acc[p][j]) : "l"(a[p]), "l"(c[j]));
            }
        }

#pragma unroll
        for (int j = 0; j < 8; ++j) {
            int k = kp * 128 + tx + 16 * j;
            float c2k = g_c2[k];
#pragma unroll
            for (int p = 0; p < 4; ++p) {
                float dlo = __uint_as_float((unsigned)(acc[p][j] & 0xffffffffull));
                float dhi = __uint_as_float((unsigned)(acc[p][j] >> 32));
                float slo = c2k - 2.0f * dlo;
                float shi = c2k - 2.0f * dhi;
                upd2(v1[2 * p],     i1[2 * p],     v2[2 * p],     i2[2 * p],     slo, k);
                upd2(v1[2 * p + 1], i1[2 * p + 1], v2[2 * p + 1], i2[2 * p + 1], shi, k);
            }
        }
    }

    __syncthreads();
#pragma unroll
    for (int p = 0; p < 8; ++p) {
        int row = rg * 8 + p;
        sm.r.v[row][2 * tx + 0]   = v1[p];
        sm.r.idx[row][2 * tx + 0] = i1[p];
        sm.r.v[row][2 * tx + 1]   = v2[p];
        sm.r.idx[row][2 * tx + 1] = i2[p];
    }
    __syncthreads();

    // per-row merge: top-4 candidate indices -> g_cand
    if (tid < ROWS) {
        int row = tid;
        int gr  = n0 + row;
        if (gr < N) {
            float V[4]; int I[4];
#pragma unroll
            for (int q = 0; q < 4; ++q) { V[q] = -__int_as_float(0x7f800000); I[q] = 0; }
            for (int j = 0; j < 32; ++j) {
                float v = sm.r.v[row][j];
                int   k = sm.r.idx[row][j];
                if (v > V[3] || (v == V[3] && k < I[3])) {
                    V[3] = v; I[3] = k;
#pragma unroll
                    for (int q = 3; q > 0; --q) {
                        if (V[q] > V[q - 1] || (V[q] == V[q - 1] && I[q] < I[q - 1])) {
                            float tv = V[q]; V[q] = V[q - 1]; V[q - 1] = tv;
                            int   ti = I[q]; I[q] = I[q - 1]; I[q - 1] = ti;
                        }
                    }
                }
            }
#pragma unroll
            for (int q = 0; q < 4; ++q) g_cand[(size_t)gr * 4 + q] = I[q];
        }
    }
}

__device__ __forceinline__ double wred(double v) {
#pragma unroll
    for (int o = 16; o; o >>= 1) v += __shfl_xor_sync(0xffffffffu, v, o);
    return v;
}

__global__ __launch_bounds__(256)
void refine_kernel(const float* __restrict__ emb,
                   const float* __restrict__ cent,
                   float* __restrict__ out, int N) {
    int row  = (blockIdx.x * blockDim.x + threadIdx.x) >> 5;
    int lane = threadIdx.x & 31;
    if (row >= N) return;

    const float4* er = reinterpret_cast<const float4*>(emb + (size_t)row * DIM);
    float4 e0 = er[lane];        // d = 4*lane .. 4*lane+3
    float4 e1 = er[lane + 32];   // d = 128 + 4*lane ..

    // x2 in fp64 (exact), then rounded to fp32 like the reference's value
    double px = (double)e0.x * e0.x + (double)e0.y * e0.y
              + (double)e0.z * e0.z + (double)e0.w * e0.w
              + (double)e1.x * e1.x + (double)e1.y * e1.y
              + (double)e1.z * e1.z + (double)e1.w * e1.w;
    float x2f = (float)wred(px);

    float V1 = -__int_as_float(0x7f800000), V2 = V1;
    int   I1 = 0, I2 = 0;

#pragma unroll
    for (int j = 0; j < 4; ++j) {
        int k = g_cand[(size_t)row * 4 + j];
        const float4* cr = reinterpret_cast<const float4*>(cent + (size_t)k * DIM);
        float4 c0 = cr[lane];
        float4 c1 = cr[lane + 32];
        double pd = (double)e0.x * c0.x + (double)e0.y * c0.y
                  + (double)e0.z * c0.z + (double)e0.w * c0.w
                  + (double)e1.x * c1.x + (double)e1.y * c1.y
                  + (double)e1.z * c1.z + (double)e1.w * c1.w;
        float xcf = (float)wred(pd);                  // correctly-rounded dot
        // reference chain: ((x2 + c2) - 2*xc) -> max(,0) -> sqrt, all fp32 rn
        float a = __fadd_rn(x2f, (float)g_c2d[k]);
        float t = __fadd_rn(a, __fmul_rn(-2.0f, xcf));
        float u = fmaxf(t, 0.0f);
        float r = __fsqrt_rn(u);
        bool b1 = (r > V1) || (r == V1 && k < I1);
        bool b2 = (r > V2) || (r == V2 && k < I2);
        if (b1) { V2 = V1; I2 = I1; V1 = r; I1 = k; }
        else if (b2) { V2 = r; I2 = k; }
    }

    // out[row] = centroids[I2] (second-largest distance), warp-cooperative copy
    const float4* src = reinterpret_cast<const float4*>(cent + (size_t)I2 * DIM);
    float4*       dst = reinterpret_cast<float4*>(out + (size_t)row * DIM);
    dst[lane]      = src[lane];
    dst[lane + 32] = src[lane + 32];
}

extern "C" void kernel_launch(void* const* d_in, const int* in_sizes, int n_in,
                              void* d_out, int out_size) {
    const float* emb  = (const float*)d_in[0];
    const float* cent = (const float*)d_in[1];
    float* out = (float*)d_out;
    int N = in_sizes[0] / DIM;

    c2_kernel<<<1, KTOT>>>(cent);
    neg_sampler_fast<<<(N + ROWS - 1) / ROWS, 256>>>(emb, cent, N);
    refine_kernel<<<(N * 32 + 255) / 256, 256>>>(emb, cent, out, N);
}